// round 2
// baseline (speedup 1.0000x reference)
#include <cuda_runtime.h>
#include <cstdint>
#include <math.h>

#define BB   32
#define SEQ  577
#define CH   1024
#define NH   16
#define HD   64
#define HIDN 4096
#define MTOK (BB*SEQ)      // 18464 tokens
#define NBH  (BB*NH)       // 512 (batch*heads)

// ---------------- static scratch (no allocations allowed) ----------------
__device__ float  g_maxabs[4];
__device__ int8_t g_wqkv [3*CH*CH];
__device__ int8_t g_wproj[CH*CH];
__device__ int8_t g_wfc1 [HIDN*CH];
__device__ int8_t g_wfc2 [CH*HIDN];
__device__ int8_t g_a1[(size_t)MTOK*CH];
__device__ int8_t g_ao[(size_t)MTOK*CH];
__device__ int8_t g_a2[(size_t)MTOK*CH];
__device__ int8_t g_a3[(size_t)MTOK*HIDN];
__device__ float  g_q [(size_t)NBH*SEQ*HD];
__device__ float  g_kk[(size_t)NBH*SEQ*HD];
__device__ float  g_v [(size_t)NBH*SEQ*HD];
__device__ float  g_S [(size_t)NBH*SEQ*SEQ];   // 682 MB attention scores
__device__ float  g_x1[(size_t)MTOK*CH];

// ---------------- weight quantization ----------------
__global__ void k_reset() { if (threadIdx.x < 4) g_maxabs[threadIdx.x] = 0.f; }

__global__ void k_absmax(const float* __restrict__ w, int n, int idx) {
    float m = 0.f;
    for (int i = blockIdx.x * blockDim.x + threadIdx.x; i < n; i += gridDim.x * blockDim.x)
        m = fmaxf(m, fabsf(w[i]));
    #pragma unroll
    for (int o = 16; o; o >>= 1) m = fmaxf(m, __shfl_xor_sync(0xffffffffu, m, o));
    if ((threadIdx.x & 31) == 0) atomicMax((int*)&g_maxabs[idx], __float_as_int(m));
}

__global__ void k_quantw(const float* __restrict__ w, int8_t* __restrict__ dst, int n, int idx) {
    // wq = 2*round((0.5*tanh(w)/max|tanh| + 0.5)*15)/15 - 1  -> store odd int in [-15,15]
    float T = tanhf(g_maxabs[idx]);   // tanh monotone: max|tanh(w)| = tanh(max|w|)
    for (int i = blockIdx.x * blockDim.x + threadIdx.x; i < n; i += gridDim.x * blockDim.x) {
        float wn = tanhf(w[i]) / T;
        int m = (int)rintf((0.5f * wn + 0.5f) * 15.0f);   // rintf == round-half-even (jnp.round)
        dst[i] = (int8_t)(2 * m - 15);
    }
}

// ---------------- LayerNorm + 4-bit activation quant ----------------
__global__ void k_ln_aq(const float* __restrict__ x, const float* __restrict__ g,
                        const float* __restrict__ bb, int8_t* __restrict__ out) {
    int t = blockIdx.x;
    int tid = threadIdx.x;                  // 256 threads
    const float* row = x + (size_t)t * CH;
    __shared__ float red[8];
    float v[4];
    float s = 0.f;
    #pragma unroll
    for (int i = 0; i < 4; i++) { v[i] = row[tid + i * 256]; s += v[i]; }
    #pragma unroll
    for (int o = 16; o; o >>= 1) s += __shfl_xor_sync(0xffffffffu, s, o);
    if ((tid & 31) == 0) red[tid >> 5] = s;
    __syncthreads();
    if (tid < 8) {
        float z = red[tid];
        #pragma unroll
        for (int o = 4; o; o >>= 1) z += __shfl_xor_sync(0xffu, z, o);
        if (tid == 0) red[0] = z;
    }
    __syncthreads();
    float mean = red[0] * (1.0f / CH);
    __syncthreads();
    float qq = 0.f;
    #pragma unroll
    for (int i = 0; i < 4; i++) { float d = v[i] - mean; qq += d * d; }
    #pragma unroll
    for (int o = 16; o; o >>= 1) qq += __shfl_xor_sync(0xffffffffu, qq, o);
    if ((tid & 31) == 0) red[tid >> 5] = qq;
    __syncthreads();
    if (tid < 8) {
        float z = red[tid];
        #pragma unroll
        for (int o = 4; o; o >>= 1) z += __shfl_xor_sync(0xffu, z, o);
        if (tid == 0) red[0] = z;
    }
    __syncthreads();
    float sd = sqrtf(red[0] * (1.0f / CH) + 1e-5f);
    #pragma unroll
    for (int i = 0; i < 4; i++) {
        int c = tid + i * 256;
        float h = (v[i] - mean) / sd * g[c] + bb[c];
        out[(size_t)t * CH + c] = (int8_t)rintf(fminf(fmaxf(h, 0.f), 1.f) * 15.0f);
    }
}

// ---------------- int8 dp4a GEMM (exact) with fused epilogues ----------------
// C[m,f] acc = sum_k A[m,k]*W[f,k];  A: [Mdim,K] int8, W: [Ndim,K] int8; Ndim = gridDim.x*64
// MODE 0: qkv  -> round(acc/15)/15 scattered into q/k/v [B,H,N,D]
// MODE 1: proj -> x + round(acc/15 + 15b)/15 into outf (x1)
// MODE 2: fc1  -> gelu(round(acc/15+15b)/15) -> aq int8 into outi
// MODE 3: fc2  -> x1 + round(7*round(acc/15+15b)/15)/7 into outf (d_out)
template<int MODE>
__global__ void gemm8(const int8_t* __restrict__ A, const int8_t* __restrict__ W,
                      int Mdim, int K,
                      const float* __restrict__ bias,
                      const float* __restrict__ resid,
                      float* __restrict__ outf, int8_t* __restrict__ outi) {
    const int K4 = K >> 2;
    __shared__ int sA[64][17];
    __shared__ int sB[64][17];
    const int tx = threadIdx.x, ty = threadIdx.y;
    const int tid = ty * 16 + tx;
    const int mbase = blockIdx.y * 64;
    const int nbase = blockIdx.x * 64;
    const int* Aw = (const int*)A;
    const int* Ww = (const int*)W;
    int acc[4][4];
    #pragma unroll
    for (int i = 0; i < 4; i++)
        #pragma unroll
        for (int j = 0; j < 4; j++) acc[i][j] = 0;

    for (int k0 = 0; k0 < K4; k0 += 16) {
        #pragma unroll
        for (int i = 0; i < 4; i++) {
            int idx = tid + i * 256;
            int r = idx >> 4, c = idx & 15;
            int gm = mbase + r;
            sA[r][c] = (gm < Mdim) ? Aw[(size_t)gm * K4 + k0 + c] : 0;
            sB[r][c] = Ww[(size_t)(nbase + r) * K4 + k0 + c];
        }
        __syncthreads();
        #pragma unroll
        for (int w = 0; w < 16; w++) {
            int a0 = sA[ty*4+0][w], a1 = sA[ty*4+1][w], a2 = sA[ty*4+2][w], a3 = sA[ty*4+3][w];
            int b0 = sB[tx*4+0][w], b1 = sB[tx*4+1][w], b2 = sB[tx*4+2][w], b3 = sB[tx*4+3][w];
            acc[0][0] = __dp4a(a0,b0,acc[0][0]); acc[0][1] = __dp4a(a0,b1,acc[0][1]);
            acc[0][2] = __dp4a(a0,b2,acc[0][2]); acc[0][3] = __dp4a(a0,b3,acc[0][3]);
            acc[1][0] = __dp4a(a1,b0,acc[1][0]); acc[1][1] = __dp4a(a1,b1,acc[1][1]);
            acc[1][2] = __dp4a(a1,b2,acc[1][2]); acc[1][3] = __dp4a(a1,b3,acc[1][3]);
            acc[2][0] = __dp4a(a2,b0,acc[2][0]); acc[2][1] = __dp4a(a2,b1,acc[2][1]);
            acc[2][2] = __dp4a(a2,b2,acc[2][2]); acc[2][3] = __dp4a(a2,b3,acc[2][3]);
            acc[3][0] = __dp4a(a3,b0,acc[3][0]); acc[3][1] = __dp4a(a3,b1,acc[3][1]);
            acc[3][2] = __dp4a(a3,b2,acc[3][2]); acc[3][3] = __dp4a(a3,b3,acc[3][3]);
        }
        __syncthreads();
    }
    #pragma unroll
    for (int i = 0; i < 4; i++) {
        int m = mbase + ty * 4 + i;
        if (m >= Mdim) continue;
        #pragma unroll
        for (int j = 0; j < 4; j++) {
            int f = nbase + tx * 4 + j;
            float a15 = (float)acc[i][j] / 15.0f;   // exact int -> margin >= 1/30 to ties
            if (MODE == 0) {
                float fv = rintf(a15) / 15.0f;
                int p = f >> 10, rem = f & 1023, h = rem >> 6, d = rem & 63;
                int b = m / SEQ, n = m - b * SEQ;
                size_t di = (((size_t)(b * NH + h)) * SEQ + n) * HD + d;
                (p == 0 ? g_q : p == 1 ? g_kk : g_v)[di] = fv;
            } else if (MODE == 1) {
                float fv = rintf(a15 + 15.0f * bias[f]) / 15.0f;
                outf[(size_t)m * CH + f] = resid[(size_t)m * CH + f] + fv;
            } else if (MODE == 2) {
                float u = rintf(a15 + 15.0f * bias[f]) / 15.0f;
                float er = erff(u / 1.41421356237309515f);
                float ge = 0.5f * u * (1.0f + er);
                outi[(size_t)m * HIDN + f] = (int8_t)rintf(fminf(fmaxf(ge, 0.f), 1.f) * 15.0f);
            } else {
                float u = rintf(a15 + 15.0f * bias[f]) / 15.0f;
                float y2 = rintf(u * 7.0f) / 7.0f;
                outf[(size_t)m * CH + f] = resid[(size_t)m * CH + f] + y2;
            }
        }
    }
}

// ---------------- attention: S = q k^T * scale ----------------
__global__ void k_qk() {
    const int bh = blockIdx.z;
    const float* q = g_q  + (size_t)bh * SEQ * HD;
    const float* k = g_kk + (size_t)bh * SEQ * HD;
    __shared__ float sq[64][65];
    __shared__ float sk[64][65];
    const int tx = threadIdx.x, ty = threadIdx.y, tid = ty * 16 + tx;
    const int n0 = blockIdx.y * 64, m0 = blockIdx.x * 64;
    #pragma unroll
    for (int i = 0; i < 16; i++) {
        int idx = tid + i * 256;
        int r = idx >> 6, c = idx & 63;
        int gn = n0 + r;
        sq[r][c] = (gn < SEQ) ? q[(size_t)gn * HD + c] : 0.f;
        int gm = m0 + r;
        sk[r][c] = (gm < SEQ) ? k[(size_t)gm * HD + c] : 0.f;
    }
    __syncthreads();
    float acc[4][4] = {};
    #pragma unroll 8
    for (int d = 0; d < 64; d++) {
        float a0 = sq[ty*4+0][d], a1 = sq[ty*4+1][d], a2 = sq[ty*4+2][d], a3 = sq[ty*4+3][d];
        float b0 = sk[tx*4+0][d], b1 = sk[tx*4+1][d], b2 = sk[tx*4+2][d], b3 = sk[tx*4+3][d];
        acc[0][0] += a0*b0; acc[0][1] += a0*b1; acc[0][2] += a0*b2; acc[0][3] += a0*b3;
        acc[1][0] += a1*b0; acc[1][1] += a1*b1; acc[1][2] += a1*b2; acc[1][3] += a1*b3;
        acc[2][0] += a2*b0; acc[2][1] += a2*b1; acc[2][2] += a2*b2; acc[2][3] += a2*b3;
        acc[3][0] += a3*b0; acc[3][1] += a3*b1; acc[3][2] += a3*b2; acc[3][3] += a3*b3;
    }
    float* S = g_S + (size_t)bh * SEQ * SEQ;
    #pragma unroll
    for (int i = 0; i < 4; i++) {
        int n = n0 + ty * 4 + i;
        if (n >= SEQ) continue;
        #pragma unroll
        for (int j = 0; j < 4; j++) {
            int m = m0 + tx * 4 + j;
            if (m >= SEQ) continue;
            S[(size_t)n * SEQ + m] = acc[i][j] * 0.125f;   // D^-0.5
        }
    }
}

// ---------------- softmax + 3-bit quant (store a*7 as float 0..7) ----------------
__global__ void k_softmax() {
    const int n = blockIdx.x, bh = blockIdx.y;
    float* row = g_S + ((size_t)bh * SEQ + n) * SEQ;
    __shared__ float buf[SEQ];
    __shared__ float red[8];
    const int tid = threadIdx.x;   // 256
    float mx = -1e30f;
    for (int i = tid; i < SEQ; i += 256) { float v = row[i]; buf[i] = v; mx = fmaxf(mx, v); }
    #pragma unroll
    for (int o = 16; o; o >>= 1) mx = fmaxf(mx, __shfl_xor_sync(0xffffffffu, mx, o));
    if ((tid & 31) == 0) red[tid >> 5] = mx;
    __syncthreads();
    if (tid < 8) {
        float z = red[tid];
        #pragma unroll
        for (int o = 4; o; o >>= 1) z = fmaxf(z, __shfl_xor_sync(0xffu, z, o));
        if (tid == 0) red[0] = z;
    }
    __syncthreads();
    mx = red[0];
    __syncthreads();
    float s = 0.f;
    for (int i = tid; i < SEQ; i += 256) { float e = expf(buf[i] - mx); buf[i] = e; s += e; }
    #pragma unroll
    for (int o = 16; o; o >>= 1) s += __shfl_xor_sync(0xffffffffu, s, o);
    if ((tid & 31) == 0) red[tid >> 5] = s;
    __syncthreads();
    if (tid < 8) {
        float z = red[tid];
        #pragma unroll
        for (int o = 4; o; o >>= 1) z += __shfl_xor_sync(0xffu, z, o);
        if (tid == 0) red[0] = z;
    }
    __syncthreads();
    float tot = red[0];
    for (int i = tid; i < SEQ; i += 256) row[i] = rintf(7.0f * (buf[i] / tot));
}

// ---------------- o = (Sq/7) @ v, fused with _aq -> int8 proj input ----------------
__global__ void k_av() {
    const int bh = blockIdx.y;
    const int n0 = blockIdx.x * 64;
    const float* S = g_S + (size_t)bh * SEQ * SEQ;
    const float* v = g_v + (size_t)bh * SEQ * HD;
    __shared__ float sS[64][33];
    __shared__ float sV[32][65];
    const int tx = threadIdx.x, ty = threadIdx.y, tid = ty * 16 + tx;
    float acc[4][4] = {};
    for (int m0 = 0; m0 < SEQ; m0 += 32) {
        #pragma unroll
        for (int i = 0; i < 8; i++) {
            int idx = tid + i * 256;
            int r = idx >> 5, c = idx & 31;
            int gn = n0 + r, gm = m0 + c;
            sS[r][c] = (gn < SEQ && gm < SEQ) ? S[(size_t)gn * SEQ + gm] : 0.f;
        }
        #pragma unroll
        for (int i = 0; i < 8; i++) {
            int idx = tid + i * 256;
            int r = idx >> 6, c = idx & 63;
            int gm = m0 + r;
            sV[r][c] = (gm < SEQ) ? v[(size_t)gm * HD + c] : 0.f;
        }
        __syncthreads();
        #pragma unroll 8
        for (int w = 0; w < 32; w++) {
            float a0 = sS[ty*4+0][w], a1 = sS[ty*4+1][w], a2 = sS[ty*4+2][w], a3 = sS[ty*4+3][w];
            float b0 = sV[w][tx*4+0], b1 = sV[w][tx*4+1], b2 = sV[w][tx*4+2], b3 = sV[w][tx*4+3];
            acc[0][0] += a0*b0; acc[0][1] += a0*b1; acc[0][2] += a0*b2; acc[0][3] += a0*b3;
            acc[1][0] += a1*b0; acc[1][1] += a1*b1; acc[1][2] += a1*b2; acc[1][3] += a1*b3;
            acc[2][0] += a2*b0; acc[2][1] += a2*b1; acc[2][2] += a2*b2; acc[2][3] += a2*b3;
            acc[3][0] += a3*b0; acc[3][1] += a3*b1; acc[3][2] += a3*b2; acc[3][3] += a3*b3;
        }
        __syncthreads();
    }
    const int b = bh >> 4, h = bh & 15;
    #pragma unroll
    for (int i = 0; i < 4; i++) {
        int n = n0 + ty * 4 + i;
        if (n >= SEQ) continue;
        #pragma unroll
        for (int j = 0; j < 4; j++) {
            int d = tx * 4 + j;
            float o = acc[i][j] * (1.0f / 7.0f);
            g_ao[((size_t)(b * SEQ + n)) * CH + h * 64 + d] =
                (int8_t)rintf(fminf(fmaxf(o, 0.f), 1.f) * 15.0f);
        }
    }
}

// ---------------- launch ----------------
extern "C" void kernel_launch(void* const* d_in, const int* in_sizes, int n_in,
                              void* d_out, int out_size) {
    const float* x     = (const float*)d_in[0];
    const float* ln1w  = (const float*)d_in[1];
    const float* ln1b  = (const float*)d_in[2];
    const float* qkvw  = (const float*)d_in[3];
    const float* projw = (const float*)d_in[4];
    const float* projb = (const float*)d_in[5];
    const float* ln2w  = (const float*)d_in[6];
    const float* ln2b  = (const float*)d_in[7];
    const float* fc1w  = (const float*)d_in[8];
    const float* fc1b  = (const float*)d_in[9];
    const float* fc2w  = (const float*)d_in[10];
    const float* fc2b  = (const float*)d_in[11];

    void *p_wqkv, *p_wproj, *p_wfc1, *p_wfc2, *p_a1, *p_ao, *p_a2, *p_a3, *p_x1;
    cudaGetSymbolAddress(&p_wqkv,  g_wqkv);
    cudaGetSymbolAddress(&p_wproj, g_wproj);
    cudaGetSymbolAddress(&p_wfc1,  g_wfc1);
    cudaGetSymbolAddress(&p_wfc2,  g_wfc2);
    cudaGetSymbolAddress(&p_a1, g_a1);
    cudaGetSymbolAddress(&p_ao, g_ao);
    cudaGetSymbolAddress(&p_a2, g_a2);
    cudaGetSymbolAddress(&p_a3, g_a3);
    cudaGetSymbolAddress(&p_x1, g_x1);

    dim3 b2(16, 16);
    k_reset<<<1, 32>>>();
    k_absmax<<<1024, 256>>>(qkvw,  3*CH*CH,  0);
    k_absmax<<<1024, 256>>>(projw, CH*CH,    1);
    k_absmax<<<1024, 256>>>(fc1w,  HIDN*CH,  2);
    k_absmax<<<1024, 256>>>(fc2w,  CH*HIDN,  3);
    k_quantw<<<2048, 256>>>(qkvw,  (int8_t*)p_wqkv,  3*CH*CH, 0);
    k_quantw<<<2048, 256>>>(projw, (int8_t*)p_wproj, CH*CH,   1);
    k_quantw<<<2048, 256>>>(fc1w,  (int8_t*)p_wfc1,  HIDN*CH, 2);
    k_quantw<<<2048, 256>>>(fc2w,  (int8_t*)p_wfc2,  CH*HIDN, 3);

    // attention branch
    k_ln_aq<<<MTOK, 256>>>(x, ln1w, ln1b, (int8_t*)p_a1);
    gemm8<0><<<dim3(48, 289), b2>>>((const int8_t*)p_a1, (const int8_t*)p_wqkv,
                                    MTOK, CH, nullptr, nullptr, nullptr, nullptr);
    k_qk<<<dim3(10, 10, NBH), b2>>>();
    k_softmax<<<dim3(SEQ, NBH), 256>>>();
    k_av<<<dim3(10, NBH), b2>>>();
    gemm8<1><<<dim3(16, 289), b2>>>((const int8_t*)p_ao, (const int8_t*)p_wproj,
                                    MTOK, CH, projb, x, (float*)p_x1, nullptr);

    // MLP branch
    k_ln_aq<<<MTOK, 256>>>((const float*)p_x1, ln2w, ln2b, (int8_t*)p_a2);
    gemm8<2><<<dim3(64, 289), b2>>>((const int8_t*)p_a2, (const int8_t*)p_wfc1,
                                    MTOK, CH, fc1b, nullptr, nullptr, (int8_t*)p_a3);
    gemm8<3><<<dim3(16, 289), b2>>>((const int8_t*)p_a3, (const int8_t*)p_wfc2,
                                    MTOK, HIDN, fc2b, (const float*)p_x1, (float*)d_out, nullptr);
}

// round 4
// speedup vs baseline: 1.2219x; 1.2219x over previous
#include <cuda_runtime.h>
#include <cstdint>
#include <math.h>

#define BB   32
#define SEQ  577
#define CH   1024
#define NH   16
#define HD   64
#define HIDN 4096
#define MTOK (BB*SEQ)      // 18464 tokens
#define NBH  (BB*NH)       // 512 (batch*heads)

// ---------------- static scratch (no allocations allowed) ----------------
__device__ float  g_maxabs[4];
__device__ __align__(16) int8_t g_wqkv [3*CH*CH];
__device__ __align__(16) int8_t g_wproj[CH*CH];
__device__ __align__(16) int8_t g_wfc1 [HIDN*CH];
__device__ __align__(16) int8_t g_wfc2 [CH*HIDN];
__device__ __align__(16) int8_t g_a1[(size_t)MTOK*CH];
__device__ __align__(16) int8_t g_ao[(size_t)MTOK*CH];
__device__ __align__(16) int8_t g_a2[(size_t)MTOK*CH];
__device__ __align__(16) int8_t g_a3[(size_t)MTOK*HIDN];
__device__ float  g_q [(size_t)NBH*SEQ*HD];
__device__ float  g_kk[(size_t)NBH*SEQ*HD];
__device__ float  g_v [(size_t)NBH*SEQ*HD];
__device__ float  g_S [(size_t)NBH*SEQ*SEQ];   // 682 MB attention scores
__device__ float  g_x1[(size_t)MTOK*CH];

// ---------------- weight quantization ----------------
__global__ void k_reset() { if (threadIdx.x < 4) g_maxabs[threadIdx.x] = 0.f; }

__global__ void k_absmax(const float* __restrict__ w, int n, int idx) {
    float m = 0.f;
    for (int i = blockIdx.x * blockDim.x + threadIdx.x; i < n; i += gridDim.x * blockDim.x)
        m = fmaxf(m, fabsf(w[i]));
    #pragma unroll
    for (int o = 16; o; o >>= 1) m = fmaxf(m, __shfl_xor_sync(0xffffffffu, m, o));
    if ((threadIdx.x & 31) == 0) atomicMax((int*)&g_maxabs[idx], __float_as_int(m));
}

__global__ void k_quantw(const float* __restrict__ w, int8_t* __restrict__ dst, int n, int idx) {
    float T = tanhf(g_maxabs[idx]);   // tanh monotone: max|tanh(w)| = tanh(max|w|)
    for (int i = blockIdx.x * blockDim.x + threadIdx.x; i < n; i += gridDim.x * blockDim.x) {
        float wn = tanhf(w[i]) / T;
        int m = (int)rintf((0.5f * wn + 0.5f) * 15.0f);   // rintf == round-half-even
        dst[i] = (int8_t)(2 * m - 15);
    }
}

// ---------------- LayerNorm + 4-bit activation quant ----------------
__global__ void k_ln_aq(const float* __restrict__ x, const float* __restrict__ g,
                        const float* __restrict__ bb, int8_t* __restrict__ out) {
    int t = blockIdx.x;
    int tid = threadIdx.x;                  // 256 threads
    const float* row = x + (size_t)t * CH;
    __shared__ float red[8];
    float v[4];
    float s = 0.f;
    #pragma unroll
    for (int i = 0; i < 4; i++) { v[i] = row[tid + i * 256]; s += v[i]; }
    #pragma unroll
    for (int o = 16; o; o >>= 1) s += __shfl_xor_sync(0xffffffffu, s, o);
    if ((tid & 31) == 0) red[tid >> 5] = s;
    __syncthreads();
    if (tid < 8) {
        float z = red[tid];
        #pragma unroll
        for (int o = 4; o; o >>= 1) z += __shfl_xor_sync(0xffu, z, o);
        if (tid == 0) red[0] = z;
    }
    __syncthreads();
    float mean = red[0] * (1.0f / CH);
    __syncthreads();
    float qq = 0.f;
    #pragma unroll
    for (int i = 0; i < 4; i++) { float d = v[i] - mean; qq += d * d; }
    #pragma unroll
    for (int o = 16; o; o >>= 1) qq += __shfl_xor_sync(0xffffffffu, qq, o);
    if ((tid & 31) == 0) red[tid >> 5] = qq;
    __syncthreads();
    if (tid < 8) {
        float z = red[tid];
        #pragma unroll
        for (int o = 4; o; o >>= 1) z += __shfl_xor_sync(0xffu, z, o);
        if (tid == 0) red[0] = z;
    }
    __syncthreads();
    float sd = sqrtf(red[0] * (1.0f / CH) + 1e-5f);
    #pragma unroll
    for (int i = 0; i < 4; i++) {
        int c = tid + i * 256;
        float h = (v[i] - mean) / sd * g[c] + bb[c];
        out[(size_t)t * CH + c] = (int8_t)rintf(fminf(fmaxf(h, 0.f), 1.f) * 15.0f);
    }
}

// ---------------- int8 tensor-core GEMM (mma.sync.m16n8k32) ----------------
__device__ __forceinline__ void ldsm4(uint32_t& r0, uint32_t& r1, uint32_t& r2, uint32_t& r3,
                                      const void* p) {
    uint32_t a = (uint32_t)__cvta_generic_to_shared(p);
    asm volatile("ldmatrix.sync.aligned.m8n8.x4.shared.b16 {%0,%1,%2,%3}, [%4];"
                 : "=r"(r0), "=r"(r1), "=r"(r2), "=r"(r3) : "r"(a));
}

__device__ __forceinline__ void imma(int* c, const uint32_t* a, const uint32_t* b) {
    asm volatile("mma.sync.aligned.m16n8k32.row.col.s32.s8.s8.s32 "
                 "{%0,%1,%2,%3},{%4,%5,%6,%7},{%8,%9},{%0,%1,%2,%3};"
                 : "+r"(c[0]), "+r"(c[1]), "+r"(c[2]), "+r"(c[3])
                 : "r"(a[0]), "r"(a[1]), "r"(a[2]), "r"(a[3]), "r"(b[0]), "r"(b[1]));
}

// C[m,f] = sum_k A[m,k]*W[f,k];  BM=128 BN=128 BK=64, 256 thr (8 warps, 2x4)
// MODE 0: qkv  -> round(acc/15)/15 scattered into q/k/v [B,H,N,D]
// MODE 1: proj -> x + round(acc/15 + 15b)/15 into outf (x1)
// MODE 2: fc1  -> gelu(round(acc/15+15b)/15) -> aq int8 into outi
// MODE 3: fc2  -> x1 + round(7*round(acc/15+15b)/15)/7 into outf (d_out)
template<int MODE>
__global__ void __launch_bounds__(256, 2)
gemm_mma(const int8_t* __restrict__ A, const int8_t* __restrict__ W,
         int Mdim, int K,
         const float* __restrict__ bias, const float* __restrict__ resid,
         float* __restrict__ outf, int8_t* __restrict__ outi) {
    __shared__ __align__(16) int8_t sA[128][80];   // 64B data + 16B pad (bank-conflict free)
    __shared__ __align__(16) int8_t sB[128][80];

    const int tid  = threadIdx.x;
    const int lane = tid & 31;
    const int w    = tid >> 5;
    const int wm   = w >> 2;          // 0..1 -> 64-row warp tile
    const int wn   = w & 3;           // 0..3 -> 32-col warp tile
    const int mbase = blockIdx.y * 128;
    const int nbase = blockIdx.x * 128;

    // global-load assignments: 512 16B chunks per tile, 2 per thread per matrix
    const int r0c = tid >> 1, k0c = (tid & 1) * 2;         // chunk pattern: rows tid/2, 2 chunks
    int4 pa[2], pb[2];
    const int KT = K >> 6;

    // prefetch tile 0
    {
        #pragma unroll
        for (int i = 0; i < 2; i++) {
            int row = r0c, kc = k0c + i;
            int gm = mbase + row;
            pa[i] = (gm < Mdim) ? *(const int4*)(A + (size_t)gm * K + kc * 16)
                                : make_int4(0, 0, 0, 0);
            pb[i] = *(const int4*)(W + (size_t)(nbase + row) * K + kc * 16);
        }
    }

    int acc[4][4][4];
    #pragma unroll
    for (int i = 0; i < 4; i++)
        #pragma unroll
        for (int j = 0; j < 4; j++)
            #pragma unroll
            for (int r = 0; r < 4; r++) acc[i][j][r] = 0;

    for (int kt = 0; kt < KT; kt++) {
        #pragma unroll
        for (int i = 0; i < 2; i++) {
            *(int4*)&sA[r0c][(k0c + i) * 16] = pa[i];
            *(int4*)&sB[r0c][(k0c + i) * 16] = pb[i];
        }
        __syncthreads();
        if (kt + 1 < KT) {
            int k0 = (kt + 1) * 64;
            #pragma unroll
            for (int i = 0; i < 2; i++) {
                int row = r0c, kc = k0c + i;
                int gm = mbase + row;
                pa[i] = (gm < Mdim) ? *(const int4*)(A + (size_t)gm * K + k0 + kc * 16)
                                    : make_int4(0, 0, 0, 0);
                pb[i] = *(const int4*)(W + (size_t)(nbase + row) * K + k0 + kc * 16);
            }
        }
        #pragma unroll
        for (int ks = 0; ks < 2; ks++) {
            const int kb = ks * 32;
            uint32_t af[4][4], bf[4][2];
            const int grp = lane >> 3, lr = lane & 7;
            #pragma unroll
            for (int mf = 0; mf < 4; mf++) {
                int row = wm * 64 + mf * 16 + lr + (grp & 1) * 8;
                int col = kb + (grp >> 1) * 16;
                ldsm4(af[mf][0], af[mf][1], af[mf][2], af[mf][3], &sA[row][col]);
            }
            #pragma unroll
            for (int h = 0; h < 2; h++) {
                int row = wn * 32 + h * 16 + lr + (grp >> 1) * 8;
                int col = kb + (grp & 1) * 16;
                uint32_t r0, r1, r2, r3;
                ldsm4(r0, r1, r2, r3, &sB[row][col]);
                bf[2*h][0] = r0; bf[2*h][1] = r1; bf[2*h+1][0] = r2; bf[2*h+1][1] = r3;
            }
            #pragma unroll
            for (int mf = 0; mf < 4; mf++)
                #pragma unroll
                for (int nf = 0; nf < 4; nf++)
                    imma(acc[mf][nf], af[mf], bf[nf]);
        }
        __syncthreads();
    }

    // epilogue
    #pragma unroll
    for (int mf = 0; mf < 4; mf++) {
        #pragma unroll
        for (int nf = 0; nf < 4; nf++) {
            #pragma unroll
            for (int r = 0; r < 4; r++) {
                int m = mbase + wm * 64 + mf * 16 + (lane >> 2) + ((r & 2) ? 8 : 0);
                int f = nbase + wn * 32 + nf * 8 + (lane & 3) * 2 + (r & 1);
                if (m >= Mdim) continue;
                float a15 = (float)acc[mf][nf][r] / 15.0f;   // exact int -> margin >= 1/30
                if (MODE == 0) {
                    float fv = rintf(a15) / 15.0f;
                    int p = f >> 10, rem = f & 1023, h = rem >> 6, d = rem & 63;
                    int b = m / SEQ, n = m - b * SEQ;
                    size_t di = (((size_t)(b * NH + h)) * SEQ + n) * HD + d;
                    (p == 0 ? g_q : p == 1 ? g_kk : g_v)[di] = fv;
                } else if (MODE == 1) {
                    float fv = rintf(a15 + 15.0f * bias[f]) / 15.0f;
                    outf[(size_t)m * CH + f] = resid[(size_t)m * CH + f] + fv;
                } else if (MODE == 2) {
                    float u = rintf(a15 + 15.0f * bias[f]) / 15.0f;
                    float ge = 0.5f * u * (1.0f + erff(u * 0.70710678118654752f));
                    outi[(size_t)m * HIDN + f] = (int8_t)rintf(fminf(fmaxf(ge, 0.f), 1.f) * 15.0f);
                } else {
                    float u = rintf(a15 + 15.0f * bias[f]) / 15.0f;
                    float y2 = rintf(u * 7.0f) / 7.0f;
                    outf[(size_t)m * CH + f] = resid[(size_t)m * CH + f] + y2;
                }
            }
        }
    }
}

// ---------------- attention: S = q k^T * scale ----------------
__global__ void k_qk() {
    const int bh = blockIdx.z;
    const float* q = g_q  + (size_t)bh * SEQ * HD;
    const float* k = g_kk + (size_t)bh * SEQ * HD;
    __shared__ float sq[64][65];
    __shared__ float sk[64][65];
    const int tx = threadIdx.x, ty = threadIdx.y, tid = ty * 16 + tx;
    const int n0 = blockIdx.y * 64, m0 = blockIdx.x * 64;
    #pragma unroll
    for (int i = 0; i < 16; i++) {
        int idx = tid + i * 256;
        int r = idx >> 6, c = idx & 63;
        int gn = n0 + r;
        sq[r][c] = (gn < SEQ) ? q[(size_t)gn * HD + c] : 0.f;
        int gm = m0 + r;
        sk[r][c] = (gm < SEQ) ? k[(size_t)gm * HD + c] : 0.f;
    }
    __syncthreads();
    float acc[4][4] = {};
    #pragma unroll 8
    for (int d = 0; d < 64; d++) {
        float a0 = sq[ty*4+0][d], a1 = sq[ty*4+1][d], a2 = sq[ty*4+2][d], a3 = sq[ty*4+3][d];
        float b0 = sk[tx*4+0][d], b1 = sk[tx*4+1][d], b2 = sk[tx*4+2][d], b3 = sk[tx*4+3][d];
        acc[0][0] += a0*b0; acc[0][1] += a0*b1; acc[0][2] += a0*b2; acc[0][3] += a0*b3;
        acc[1][0] += a1*b0; acc[1][1] += a1*b1; acc[1][2] += a1*b2; acc[1][3] += a1*b3;
        acc[2][0] += a2*b0; acc[2][1] += a2*b1; acc[2][2] += a2*b2; acc[2][3] += a2*b3;
        acc[3][0] += a3*b0; acc[3][1] += a3*b1; acc[3][2] += a3*b2; acc[3][3] += a3*b3;
    }
    float* S = g_S + (size_t)bh * SEQ * SEQ;
    #pragma unroll
    for (int i = 0; i < 4; i++) {
        int n = n0 + ty * 4 + i;
        if (n >= SEQ) continue;
        #pragma unroll
        for (int j = 0; j < 4; j++) {
            int m = m0 + tx * 4 + j;
            if (m >= SEQ) continue;
            S[(size_t)n * SEQ + m] = acc[i][j] * 0.125f;
        }
    }
}

// ---------------- softmax + 3-bit quant (store a*7 as float 0..7) ----------------
__global__ void k_softmax() {
    const int n = blockIdx.x, bh = blockIdx.y;
    float* row = g_S + ((size_t)bh * SEQ + n) * SEQ;
    __shared__ float buf[SEQ];
    __shared__ float red[8];
    const int tid = threadIdx.x;   // 256
    float mx = -1e30f;
    for (int i = tid; i < SEQ; i += 256) { float v = row[i]; buf[i] = v; mx = fmaxf(mx, v); }
    #pragma unroll
    for (int o = 16; o; o >>= 1) mx = fmaxf(mx, __shfl_xor_sync(0xffffffffu, mx, o));
    if ((tid & 31) == 0) red[tid >> 5] = mx;
    __syncthreads();
    if (tid < 8) {
        float z = red[tid];
        #pragma unroll
        for (int o = 4; o; o >>= 1) z = fmaxf(z, __shfl_xor_sync(0xffu, z, o));
        if (tid == 0) red[0] = z;
    }
    __syncthreads();
    mx = red[0];
    __syncthreads();
    float s = 0.f;
    for (int i = tid; i < SEQ; i += 256) { float e = expf(buf[i] - mx); buf[i] = e; s += e; }
    #pragma unroll
    for (int o = 16; o; o >>= 1) s += __shfl_xor_sync(0xffffffffu, s, o);
    if ((tid & 31) == 0) red[tid >> 5] = s;
    __syncthreads();
    if (tid < 8) {
        float z = red[tid];
        #pragma unroll
        for (int o = 4; o; o >>= 1) z += __shfl_xor_sync(0xffu, z, o);
        if (tid == 0) red[0] = z;
    }
    __syncthreads();
    float tot = red[0];
    for (int i = tid; i < SEQ; i += 256) row[i] = rintf(7.0f * (buf[i] / tot));
}

// ---------------- o = (Sq/7) @ v, fused with _aq -> int8 proj input ----------------
__global__ void k_av() {
    const int bh = blockIdx.y;
    const int n0 = blockIdx.x * 64;
    const float* S = g_S + (size_t)bh * SEQ * SEQ;
    const float* v = g_v + (size_t)bh * SEQ * HD;
    __shared__ float sS[64][33];
    __shared__ float sV[32][65];
    const int tx = threadIdx.x, ty = threadIdx.y, tid = ty * 16 + tx;
    float acc[4][4] = {};
    for (int m0 = 0; m0 < SEQ; m0 += 32) {
        #pragma unroll
        for (int i = 0; i < 8; i++) {
            int idx = tid + i * 256;
            int r = idx >> 5, c = idx & 31;
            int gn = n0 + r, gm = m0 + c;
            sS[r][c] = (gn < SEQ && gm < SEQ) ? S[(size_t)gn * SEQ + gm] : 0.f;
        }
        #pragma unroll
        for (int i = 0; i < 8; i++) {
            int idx = tid + i * 256;
            int r = idx >> 6, c = idx & 63;
            int gm = m0 + r;
            sV[r][c] = (gm < SEQ) ? v[(size_t)gm * HD + c] : 0.f;
        }
        __syncthreads();
        #pragma unroll 8
        for (int w = 0; w < 32; w++) {
            float a0 = sS[ty*4+0][w], a1 = sS[ty*4+1][w], a2 = sS[ty*4+2][w], a3 = sS[ty*4+3][w];
            float b0 = sV[w][tx*4+0], b1 = sV[w][tx*4+1], b2 = sV[w][tx*4+2], b3 = sV[w][tx*4+3];
            acc[0][0] += a0*b0; acc[0][1] += a0*b1; acc[0][2] += a0*b2; acc[0][3] += a0*b3;
            acc[1][0] += a1*b0; acc[1][1] += a1*b1; acc[1][2] += a1*b2; acc[1][3] += a1*b3;
            acc[2][0] += a2*b0; acc[2][1] += a2*b1; acc[2][2] += a2*b2; acc[2][3] += a2*b3;
            acc[3][0] += a3*b0; acc[3][1] += a3*b1; acc[3][2] += a3*b2; acc[3][3] += a3*b3;
        }
        __syncthreads();
    }
    const int b = bh >> 4, h = bh & 15;
    #pragma unroll
    for (int i = 0; i < 4; i++) {
        int n = n0 + ty * 4 + i;
        if (n >= SEQ) continue;
        #pragma unroll
        for (int j = 0; j < 4; j++) {
            int d = tx * 4 + j;
            float o = acc[i][j] * (1.0f / 7.0f);
            g_ao[((size_t)(b * SEQ + n)) * CH + h * 64 + d] =
                (int8_t)rintf(fminf(fmaxf(o, 0.f), 1.f) * 15.0f);
        }
    }
}

// ---------------- launch ----------------
extern "C" void kernel_launch(void* const* d_in, const int* in_sizes, int n_in,
                              void* d_out, int out_size) {
    const float* x     = (const float*)d_in[0];
    const float* ln1w  = (const float*)d_in[1];
    const float* ln1b  = (const float*)d_in[2];
    const float* qkvw  = (const float*)d_in[3];
    const float* projw = (const float*)d_in[4];
    const float* projb = (const float*)d_in[5];
    const float* ln2w  = (const float*)d_in[6];
    const float* ln2b  = (const float*)d_in[7];
    const float* fc1w  = (const float*)d_in[8];
    const float* fc1b  = (const float*)d_in[9];
    const float* fc2w  = (const float*)d_in[10];
    const float* fc2b  = (const float*)d_in[11];

    void *p_wqkv, *p_wproj, *p_wfc1, *p_wfc2, *p_a1, *p_ao, *p_a2, *p_a3, *p_x1;
    cudaGetSymbolAddress(&p_wqkv,  g_wqkv);
    cudaGetSymbolAddress(&p_wproj, g_wproj);
    cudaGetSymbolAddress(&p_wfc1,  g_wfc1);
    cudaGetSymbolAddress(&p_wfc2,  g_wfc2);
    cudaGetSymbolAddress(&p_a1, g_a1);
    cudaGetSymbolAddress(&p_ao, g_ao);
    cudaGetSymbolAddress(&p_a2, g_a2);
    cudaGetSymbolAddress(&p_a3, g_a3);
    cudaGetSymbolAddress(&p_x1, g_x1);

    const int MB = (MTOK + 127) / 128;   // 145
    k_reset<<<1, 32>>>();
    k_absmax<<<1024, 256>>>(qkvw,  3*CH*CH,  0);
    k_absmax<<<1024, 256>>>(projw, CH*CH,    1);
    k_absmax<<<1024, 256>>>(fc1w,  HIDN*CH,  2);
    k_absmax<<<1024, 256>>>(fc2w,  CH*HIDN,  3);
    k_quantw<<<2048, 256>>>(qkvw,  (int8_t*)p_wqkv,  3*CH*CH, 0);
    k_quantw<<<2048, 256>>>(projw, (int8_t*)p_wproj, CH*CH,   1);
    k_quantw<<<2048, 256>>>(fc1w,  (int8_t*)p_wfc1,  HIDN*CH, 2);
    k_quantw<<<2048, 256>>>(fc2w,  (int8_t*)p_wfc2,  CH*HIDN, 3);

    // attention branch
    k_ln_aq<<<MTOK, 256>>>(x, ln1w, ln1b, (int8_t*)p_a1);
    gemm_mma<0><<<dim3(24, MB), 256>>>((const int8_t*)p_a1, (const int8_t*)p_wqkv,
                                       MTOK, CH, nullptr, nullptr, nullptr, nullptr);
    k_qk<<<dim3(10, 10, NBH), dim3(16, 16)>>>();
    k_softmax<<<dim3(SEQ, NBH), 256>>>();
    k_av<<<dim3(10, NBH), dim3(16, 16)>>>();
    gemm_mma<1><<<dim3(8, MB), 256>>>((const int8_t*)p_ao, (const int8_t*)p_wproj,
                                      MTOK, CH, projb, x, (float*)p_x1, nullptr);

    // MLP branch
    k_ln_aq<<<MTOK, 256>>>((const float*)p_x1, ln2w, ln2b, (int8_t*)p_a2);
    gemm_mma<2><<<dim3(32, MB), 256>>>((const int8_t*)p_a2, (const int8_t*)p_wfc1,
                                       MTOK, CH, fc1b, nullptr, nullptr, (int8_t*)p_a3);
    gemm_mma<3><<<dim3(8, MB), 256>>>((const int8_t*)p_a3, (const int8_t*)p_wfc2,
                                      MTOK, HIDN, fc2b, (const float*)p_x1, (float*)d_out, nullptr);
}